// round 10
// baseline (speedup 1.0000x reference)
#include <cuda_runtime.h>

// B=64, T=512, E=8192
// out[b][j] = (1/count) * sum_{r=r0}^{511} x[b*T*E + (j+512) + r*8191]
//   r0 = max(0, j - 7679), count = 512 - r0, j in [0, 8190].
//
// Two-phase: phase 1 computes partial sums over 8 r-slices (16384 uniform
// CTAs -> ~14 waves, amortizing the drain tail); phase 2 combines (float4).

#define B_DIM 64
#define T_DIM 512
#define E_DIM 8192
#define OUT_COLS (E_DIM - 1)          // 8191
#define ROW_STRIDE (E_DIM - 1)        // 8191
#define J_FULL (E_DIM - T_DIM - 1)    // 7679
#define BLOCK 256
#define JTILES (E_DIM / BLOCK)        // 32
#define FULL_TILES 30                 // tiles 0..29: j <= 7679 (full count)
#define NQ 8
#define R_Q (T_DIM / NQ)              // 64 rows per slice
#define R_H (R_Q / 2)                 // 32 rows per stream
#define H_OFF ((unsigned)(R_H * ROW_STRIDE))

// Partial sums: [q][b][j] (16 MB scratch)
__device__ float g_part[NQ * B_DIM * E_DIM];

__global__ __launch_bounds__(BLOCK, 8) void antidiag_partial_kernel(
    const float* __restrict__ x)
{
    const int tid = threadIdx.x;
    const int b   = blockIdx.y;
    const int q   = blockIdx.z;
    const int j   = blockIdx.x * BLOCK + tid;
    if (j >= OUT_COLS) return;

    const float* __restrict__ p =
        x + (size_t)b * T_DIM * E_DIM + (size_t)(j + T_DIM);
    const int rbeg = q * R_Q;

    float s = 0.0f;
    if (blockIdx.x < FULL_TILES) {
        // hot path: full slice, two 32-row streams, unroll 8 -> 16-LDG window
        const float* ph = p + (size_t)rbeg * ROW_STRIDE;
        float s0 = 0.f, s1 = 0.f;
        #pragma unroll 8
        for (int r = 0; r < R_H; ++r) {
            const unsigned off = (unsigned)(r * ROW_STRIDE);
            s0 += ph[off];
            s1 += ph[off + H_OFF];
        }
        s = s0 + s1;
    } else {
        // ragged tail (j in [7680, 8190]): clamp slice start to r0
        const int r0 = j - J_FULL;               // >= 1 here
        const int rs = (r0 > rbeg) ? r0 : rbeg;
        const int re = rbeg + R_Q;
        #pragma unroll 8
        for (int r = rs; r < re; ++r)
            s += p[(unsigned)(r * ROW_STRIDE)];
    }

    g_part[((size_t)q * B_DIM + b) * E_DIM + j] = s;
}

// Combine: 4 consecutive j per thread, float4 loads from each quarter slice.
__global__ __launch_bounds__(BLOCK) void antidiag_combine_kernel(
    float* __restrict__ out)
{
    const int tid = threadIdx.x;
    const int b   = blockIdx.y;
    const int j4  = (blockIdx.x * BLOCK + tid) * 4;   // j4 % 4 == 0
    if (j4 >= OUT_COLS) return;

    float4 acc = make_float4(0.f, 0.f, 0.f, 0.f);
    #pragma unroll
    for (int q = 0; q < NQ; ++q) {
        const float4 v = *reinterpret_cast<const float4*>(
            &g_part[((size_t)q * B_DIM + b) * E_DIM + j4]);
        acc.x += v.x; acc.y += v.y; acc.z += v.z; acc.w += v.w;
    }

    float* ob = out + (size_t)b * OUT_COLS;
    const float r[4] = {acc.x, acc.y, acc.z, acc.w};
    #pragma unroll
    for (int k = 0; k < 4; ++k) {
        const int j = j4 + k;
        if (j < OUT_COLS) {
            const int r0 = (j > J_FULL) ? (j - J_FULL) : 0;
            ob[j] = r[k] * (1.0f / (float)(T_DIM - r0));
        }
    }
}

extern "C" void kernel_launch(void* const* d_in, const int* in_sizes, int n_in,
                              void* d_out, int out_size)
{
    const float* x = (const float*)d_in[0];
    float* out = (float*)d_out;

    dim3 block(BLOCK);
    dim3 grid1(JTILES, B_DIM, NQ);   // 32 x 64 x 8 = 16384 CTAs
    antidiag_partial_kernel<<<grid1, block>>>(x);

    dim3 grid2(E_DIM / (BLOCK * 4), B_DIM);   // 8 x 64 = 512 CTAs
    antidiag_combine_kernel<<<grid2, block>>>(out);
}

// round 11
// speedup vs baseline: 1.0106x; 1.0106x over previous
#include <cuda_runtime.h>

// B=64, T=512, E=8192
// out[b][j] = (1/count) * sum_{r=r0}^{511} x[b*T*E + (j+512) + r*8191]
//   r0 = max(0, j - 7679), count = 512 - r0, j in [0, 8190].
//
// Two-phase: phase 1 computes partial sums over 4 r-quarters (8192 uniform
// CTAs -> ~7 waves, amortizing the drain tail), 32-LDG scoreboard window;
// phase 2 combines with aligned float4 loads.

#define B_DIM 64
#define T_DIM 512
#define E_DIM 8192
#define OUT_COLS (E_DIM - 1)          // 8191
#define ROW_STRIDE (E_DIM - 1)        // 8191
#define J_FULL (E_DIM - T_DIM - 1)    // 7679
#define BLOCK 256
#define JTILES (E_DIM / BLOCK)        // 32
#define FULL_TILES 30                 // tiles 0..29: j <= 7679 (full count)
#define NQ 4
#define R_Q (T_DIM / NQ)              // 128 rows per quarter
#define R_S (R_Q / 4)                 // 32 rows per stream
#define S_OFF ((unsigned)(R_S * ROW_STRIDE))

// Partial sums: [q][b][j] (8 MB scratch)
__device__ float g_part[NQ * B_DIM * E_DIM];

__global__ __launch_bounds__(BLOCK, 8) void antidiag_partial_kernel(
    const float* __restrict__ x)
{
    const int tid = threadIdx.x;
    const int b   = blockIdx.y;
    const int q   = blockIdx.z;
    const int j   = blockIdx.x * BLOCK + tid;
    if (j >= OUT_COLS) return;

    const float* __restrict__ p =
        x + (size_t)b * T_DIM * E_DIM + (size_t)(j + T_DIM);
    const int rbeg = q * R_Q;

    float s = 0.0f;
    if (blockIdx.x < FULL_TILES) {
        // hot path: full quarter, four 32-row streams, unroll 8
        // -> 32 independent LDGs per scoreboard window.
        const float* ph = p + (size_t)rbeg * ROW_STRIDE;
        float s0 = 0.f, s1 = 0.f, s2 = 0.f, s3 = 0.f;
        #pragma unroll 8
        for (int r = 0; r < R_S; ++r) {
            const unsigned off = (unsigned)(r * ROW_STRIDE);
            s0 += ph[off];
            s1 += ph[off + S_OFF];
            s2 += ph[off + 2u * S_OFF];
            s3 += ph[off + 3u * S_OFF];
        }
        s = (s0 + s1) + (s2 + s3);
    } else {
        // ragged tail (j in [7680, 8190]): clamp quarter start to r0
        const int r0 = j - J_FULL;               // >= 1 here
        const int rs = (r0 > rbeg) ? r0 : rbeg;
        const int re = rbeg + R_Q;
        #pragma unroll 8
        for (int r = rs; r < re; ++r)
            s += p[(unsigned)(r * ROW_STRIDE)];
    }

    g_part[((size_t)q * B_DIM + b) * E_DIM + j] = s;
}

// Combine: 4 consecutive j per thread via aligned float4 loads from scratch.
// BLOCK=128 -> 1024 CTAs (parallelism) with 4-wide loads. Stores stay scalar
// (out rows have stride 8191, so float4 stores would be misaligned for b odd).
#define CBLOCK 128

__global__ __launch_bounds__(CBLOCK) void antidiag_combine_kernel(
    float* __restrict__ out)
{
    const int tid = threadIdx.x;
    const int b   = blockIdx.y;
    const int j4  = (blockIdx.x * CBLOCK + tid) * 4;   // j4 % 4 == 0, aligned
    if (j4 >= OUT_COLS) return;

    float4 acc = make_float4(0.f, 0.f, 0.f, 0.f);
    #pragma unroll
    for (int q = 0; q < NQ; ++q) {
        const float4 v = *reinterpret_cast<const float4*>(
            &g_part[((size_t)q * B_DIM + b) * E_DIM + j4]);
        acc.x += v.x; acc.y += v.y; acc.z += v.z; acc.w += v.w;
    }

    float* ob = out + (size_t)b * OUT_COLS;
    const float r[4] = {acc.x, acc.y, acc.z, acc.w};
    #pragma unroll
    for (int k = 0; k < 4; ++k) {
        const int j = j4 + k;
        if (j < OUT_COLS) {
            const int r0 = (j > J_FULL) ? (j - J_FULL) : 0;
            ob[j] = r[k] * (1.0f / (float)(T_DIM - r0));
        }
    }
}

extern "C" void kernel_launch(void* const* d_in, const int* in_sizes, int n_in,
                              void* d_out, int out_size)
{
    const float* x = (const float*)d_in[0];
    float* out = (float*)d_out;

    dim3 block(BLOCK);
    dim3 grid1(JTILES, B_DIM, NQ);   // 32 x 64 x 4 = 8192 CTAs
    antidiag_partial_kernel<<<grid1, block>>>(x);

    dim3 block2(CBLOCK);
    dim3 grid2(E_DIM / (CBLOCK * 4), B_DIM);   // 16 x 64 = 1024 CTAs
    antidiag_combine_kernel<<<grid2, block2>>>(out);
}